// round 13
// baseline (speedup 1.0000x reference)
#include <cuda_runtime.h>
#include <cstdint>

// Problem constants (B=64, C=512, H=W=28, G=8)
#define HWN    784
#define HW4    196
#define CPG    64
#define EPS    1e-5f
#define NTHR   256
#define NTILE  512
#define CSZ    4

#define SLABP   196                   // spatial positions per CTA
#define SLABF4  49                    // float4 per channel row slab
#define SLAB_T  (CPG * SLABF4)        // 3136 float4 per CTA slab
#define TILE_FLOATS (CPG * HWN)       // 50176
#define ROWF4   (HWN / 4)             // 196 float4 per full channel row

// smem layout (floats)
#define OFF_PM    (CPG * SLABP)       // 12544 : s_pm[4][64] partial ch-sums
#define OFF_PQ    (OFF_PM + 256)      // s_pq[4][2] partial stats
#define OFF_MYPM  (OFF_PQ + 8)        // 64 local partial means
#define OFF_MEANS (OFF_MYPM + 64)     // 64 final means
#define OFF_GATE  (OFF_MEANS + 64)    // 196 gate (16B aligned: 12936*4%16==0)
#define OFF_RED   (OFF_GATE + 196)    // 16 warp stat partials
#define OFF_MBAR  (OFF_RED + 16)      // 13148: even -> 8B aligned; 2 x u64
#define SMEM_FLOATS (OFF_MBAR + 4)
#define SMEM_BYTES  (SMEM_FLOATS * 4) // 52608 B -> 4 CTAs/SM

__device__ __forceinline__ uint32_t smem_u32(const void* p) {
    uint32_t a;
    asm("{ .reg .u64 t; cvta.to.shared.u64 t, %1; cvt.u32.u64 %0, t; }"
        : "=r"(a) : "l"(p));
    return a;
}

__device__ __forceinline__ uint32_t mapa_u32(uint32_t laddr, int peer) {
    uint32_t r;
    asm("mapa.shared::cluster.u32 %0, %1, %2;" : "=r"(r) : "r"(laddr), "r"(peer));
    return r;
}

// wait with cluster-scope acquire (must see peers' DSMEM stores)
__device__ __forceinline__ void mbar_wait_cl(uint32_t mbar) {
    asm volatile(
        "{\n\t"
        ".reg .pred P;\n\t"
        "WL_%=: mbarrier.try_wait.parity.acquire.cluster.shared::cta.b64 P, [%0], 0, 0x989680;\n\t"
        "@P bra WD_%=;\n\t"
        "bra WL_%=;\n\t"
        "WD_%=:\n\t"
        "}" :: "r"(mbar) : "memory");
}

__global__ __launch_bounds__(NTHR, 4) __cluster_dims__(CSZ, 1, 1)
void simam_spatial_kernel(const float* __restrict__ x,
                          const float* __restrict__ weight,
                          const float* __restrict__ bias,
                          float* __restrict__ out)
{
    extern __shared__ float smem[];
    float4* slab4   = (float4*)smem;
    float*  s_pm    = smem + OFF_PM;      // [4][64]
    float*  s_pq    = smem + OFF_PQ;      // [4][2]
    float*  s_mypm  = smem + OFF_MYPM;
    float*  s_means = smem + OFF_MEANS;
    float*  s_gate  = smem + OFF_GATE;
    float4* s_gate4 = (float4*)s_gate;
    float*  s_red   = smem + OFF_RED;
    const uint32_t mb_means = smem_u32(smem + OFF_MBAR);
    const uint32_t mb_stats = mb_means + 8;

    const int rank = (int)(blockIdx.x & (CSZ - 1));
    const int bg   = (int)(blockIdx.x >> 2);
    const int g    = bg & 7;
    const float4* xin  = (const float4*)(x + (size_t)bg * TILE_FLOATS);
    float4*       oout = (float4*)(out + (size_t)bg * TILE_FLOATS);
    const int colbase = rank * SLABF4;

    const int tid  = threadIdx.x;
    const int w    = tid >> 5;
    const int lane = tid & 31;

    // ---- init mbarriers ----
    if (tid == 0) {
        // means: 4 source CTAs x 64 threads arrive each
        asm volatile("mbarrier.init.shared::cta.b64 [%0], 256;" :: "r"(mb_means) : "memory");
        // stats: 4 source CTAs x 1 thread
        asm volatile("mbarrier.init.shared::cta.b64 [%0], 4;"   :: "r"(mb_stats) : "memory");
    }
    __syncthreads();

    // ---- load slab via cp.async (fire-and-forget into smem) ----
    {
        const uint32_t sdst = smem_u32(slab4);
        for (int i = tid; i < SLAB_T; i += NTHR) {
            const int row = i / SLABF4;
            const int col = i - row * SLABF4;
            const float4* src = xin + row * ROWF4 + colbase + col;
            asm volatile("cp.async.cg.shared.global [%0], [%1], 16;"
                         :: "r"(sdst + (uint32_t)i * 16), "l"(src) : "memory");
        }
        asm volatile("cp.async.commit_group;" ::: "memory");
    }
    // one aligned cluster sync at start: guarantees peers' mbar init is visible
    // before any remote arrive lands; overlapped with the in-flight loads
    asm volatile("barrier.cluster.arrive.aligned;" ::: "memory");
    asm volatile("barrier.cluster.wait.aligned;"   ::: "memory");
    asm volatile("cp.async.wait_group 0;" ::: "memory");
    __syncthreads();

    // ---- partial per-channel sums over our 196 positions (warp w: ch 8w..8w+7)
    #pragma unroll
    for (int q = 0; q < 8; q++) {
        const int c = w * 8 + q;
        const float4* r4 = slab4 + c * SLABF4;
        float cs = 0.f;
        if (lane < SLABF4) {
            float4 v = r4[lane];
            cs += (v.x + v.y) + (v.z + v.w);
        }
        if (lane + 32 < SLABF4) {
            float4 v = r4[lane + 32];
            cs += (v.x + v.y) + (v.z + v.w);
        }
        #pragma unroll
        for (int o = 16; o; o >>= 1) cs += __shfl_xor_sync(0xffffffffu, cs, o);
        if (lane == 0) s_mypm[c] = cs;
    }
    __syncthreads();

    // ---- broadcast partial ch-sums to all 4 CTAs' s_pm[rank][*] + arrive ----
    if (tid < CPG) {
        const float pv = s_mypm[tid];
        const uint32_t l_slot = smem_u32(&s_pm[rank * CPG + tid]);
        #pragma unroll
        for (int d = 0; d < CSZ; d++) {
            const uint32_t ra = mapa_u32(l_slot, d);
            const uint32_t rb = mapa_u32(mb_means, d);
            asm volatile("st.shared::cluster.f32 [%0], %1;" :: "r"(ra), "f"(pv) : "memory");
            asm volatile("mbarrier.arrive.release.cluster.shared::cluster.b64 _, [%0];"
                         :: "r"(rb) : "memory");
        }
    }
    mbar_wait_cl(mb_means);

    // ---- finalize means ----
    if (tid < CPG) {
        s_means[tid] = (s_pm[tid] + s_pm[CPG + tid] + s_pm[2 * CPG + tid]
                        + s_pm[3 * CPG + tid]) * (1.0f / HWN);
    }
    __syncthreads();

    // ---- local s-fold over 64 channels (threads 0..195, scalar positions) ----
    float sv = 0.f;
    if (tid < SLABP) {
        const float* colp = smem + tid;        // slab[c*196 + tid]
        #pragma unroll 8
        for (int c = 0; c < CPG; c++)
            sv += s_means[c] * colp[c * SLABP];
    }
    // ---- local partial stats ----
    float ls = sv, lq = sv * sv;
    #pragma unroll
    for (int o = 16; o; o >>= 1) {
        ls += __shfl_xor_sync(0xffffffffu, ls, o);
        lq += __shfl_xor_sync(0xffffffffu, lq, o);
    }
    if (lane == 0) { s_red[w] = ls; s_red[8 + w] = lq; }
    __syncthreads();
    if (tid == 0) {
        float ts = 0.f, tq = 0.f;
        #pragma unroll
        for (int i = 0; i < 8; i++) { ts += s_red[i]; tq += s_red[8 + i]; }
        const uint32_t l0 = smem_u32(&s_pq[rank * 2]);
        #pragma unroll
        for (int d = 0; d < CSZ; d++) {
            const uint32_t ra = mapa_u32(l0, d);
            const uint32_t rb = mapa_u32(mb_stats, d);
            asm volatile("st.shared::cluster.f32 [%0], %1;" :: "r"(ra),     "f"(ts) : "memory");
            asm volatile("st.shared::cluster.f32 [%0], %1;" :: "r"(ra + 4), "f"(tq) : "memory");
            asm volatile("mbarrier.arrive.release.cluster.shared::cluster.b64 _, [%0];"
                         :: "r"(rb) : "memory");
        }
    }
    mbar_wait_cl(mb_stats);

    // ---- final stats + gate (all data local now) ----
    {
        const float ts = s_pq[0] + s_pq[2] + s_pq[4] + s_pq[6];
        const float tq = s_pq[1] + s_pq[3] + s_pq[5] + s_pq[7];
        const float mu  = ts * (1.0f / HWN);
        const float var = tq * (1.0f / HWN) - mu * mu;
        const float rs  = rsqrtf(var + EPS);
        if (tid < SLABP) {
            const float wg = weight[g];
            const float bb = bias[g];
            const float t  = (sv - mu) * rs * wg + bb;
            s_gate[tid] = 1.0f / (1.0f + __expf(-t));
        }
    }
    __syncthreads();

    // ---- multiply + store ----
    for (int i = tid; i < SLAB_T; i += NTHR) {
        const int row = i / SLABF4;
        const int col = i - row * SLABF4;
        float4 v = slab4[i];
        const float4 gt = s_gate4[col];
        v.x *= gt.x; v.y *= gt.y; v.z *= gt.z; v.w *= gt.w;
        oout[row * ROWF4 + colbase + col] = v;
    }
}

extern "C" void kernel_launch(void* const* d_in, const int* in_sizes, int n_in,
                              void* d_out, int out_size)
{
    const float* x  = (const float*)d_in[0];
    const float* wt = (const float*)d_in[1];
    const float* bs = (const float*)d_in[2];
    float* out = (float*)d_out;

    cudaFuncSetAttribute(simam_spatial_kernel,
                         cudaFuncAttributeMaxDynamicSharedMemorySize, SMEM_BYTES);
    simam_spatial_kernel<<<NTILE * CSZ, NTHR, SMEM_BYTES>>>(x, wt, bs, out);
}

// round 16
// speedup vs baseline: 1.5325x; 1.5325x over previous
#include <cuda_runtime.h>
#include <cstdint>

// Problem constants (B=64, C=512, H=W=28, G=8)
#define HWN    784
#define HW4    196
#define CPG    64
#define EPS    1e-5f
#define NTHR   1024      // 32 warps
#define NTILE  512
#define GRID   148

#define TILE_FLOATS (CPG * HWN)       // 50176

// smem layout (floats)
#define OFF_GATE  TILE_FLOATS         // 784 gate scalars (16B aligned)
#define OFF_MEANS (OFF_GATE + HWN)    // 64 channel means
#define OFF_RED   (OFF_MEANS + CPG)   // 66 scratch: [0..31] sum, [32..63] sq, [64] mu, [65] rsig
#define SMEM_FLOATS (OFF_RED + 66)
#define SMEM_BYTES  (SMEM_FLOATS * 4) // ~204.4 KB -> 1 CTA/SM

__global__ __launch_bounds__(NTHR, 1)
void simam_wide_kernel(const float* __restrict__ x,
                       const float* __restrict__ weight,
                       const float* __restrict__ bias,
                       float* __restrict__ out)
{
    extern __shared__ float smem[];
    float*  s_gate  = smem + OFF_GATE;
    float4* s_gate4 = (float4*)s_gate;
    float*  s_means = smem + OFF_MEANS;
    float*  s_red   = smem + OFF_RED;

    const int tid  = threadIdx.x;
    const int w    = tid >> 5;        // 0..31
    const int lane = tid & 31;

    for (int tile = blockIdx.x; tile < NTILE; tile += GRID) {
        const int g = tile & 7;
        const float* xt = x   + (size_t)tile * TILE_FLOATS;
        float*       ot = out + (size_t)tile * TILE_FLOATS;

        // ===== Phase 1: load 64x784 tile to smem + per-channel means =====
        // warp w handles channels w and w+32; 14 LDG.128 in flight per warp.
        {
            const int c0 = w;
            const int c1 = w + 32;
            const float4* r0 = (const float4*)(xt + c0 * HWN);
            const float4* r1 = (const float4*)(xt + c1 * HWN);
            float4 v0[7], v1[7];
            #pragma unroll
            for (int k = 0; k < 7; k++) {
                const int j = lane + 32 * k;
                if (j < HW4) { v0[k] = __ldg(r0 + j); v1[k] = __ldg(r1 + j); }
            }
            float cs0 = 0.f, cs1 = 0.f;
            float4* s0 = (float4*)(smem + c0 * HWN);
            float4* s1 = (float4*)(smem + c1 * HWN);
            #pragma unroll
            for (int k = 0; k < 7; k++) {
                const int j = lane + 32 * k;
                if (j < HW4) {
                    s0[j] = v0[k];
                    s1[j] = v1[k];
                    cs0 += (v0[k].x + v0[k].y) + (v0[k].z + v0[k].w);
                    cs1 += (v1[k].x + v1[k].y) + (v1[k].z + v1[k].w);
                }
            }
            #pragma unroll
            for (int o = 16; o; o >>= 1) {
                cs0 += __shfl_xor_sync(0xffffffffu, cs0, o);
                cs1 += __shfl_xor_sync(0xffffffffu, cs1, o);
            }
            if (lane == 0) {
                s_means[c0] = cs0 * (1.0f / HWN);
                s_means[c1] = cs1 * (1.0f / HWN);
            }
        }
        __syncthreads();

        // ===== Phase 2: scalar s-fold (784 threads, conflict-free LDS) =====
        float sv = 0.f;
        if (tid < HWN) {
            const float* colp = smem + tid;          // smem[c*784 + tid]
            #pragma unroll 8
            for (int c = 0; c < CPG; c++)
                sv += s_means[c] * colp[c * HWN];
        }
        // stats over 784 values (inactive threads contribute 0)
        float ls = sv, lq = sv * sv;
        #pragma unroll
        for (int o = 16; o; o >>= 1) {
            ls += __shfl_xor_sync(0xffffffffu, ls, o);
            lq += __shfl_xor_sync(0xffffffffu, lq, o);
        }
        if (lane == 0) { s_red[w] = ls; s_red[32 + w] = lq; }
        __syncthreads();
        if (tid == 0) {
            float ts = 0.f, tq = 0.f;
            #pragma unroll
            for (int i = 0; i < 32; i++) { ts += s_red[i]; tq += s_red[32 + i]; }
            const float mu  = ts * (1.0f / HWN);
            const float var = tq * (1.0f / HWN) - mu * mu;
            s_red[64] = mu;
            s_red[65] = rsqrtf(var + EPS);
        }
        __syncthreads();

        // ===== Phase 3: gate =====
        {
            const float mu = s_red[64];
            const float rs = s_red[65];
            const float wg = weight[g];
            const float bb = bias[g];
            if (tid < HWN) {
                const float t = (sv - mu) * rs * wg + bb;
                s_gate[tid] = 1.0f / (1.0f + __expf(-t));
            }
        }
        __syncthreads();

        // ===== Phase 4: multiply + store (fire-and-forget STG) =====
        {
            const int c0 = w;
            const int c1 = w + 32;
            const float4* s0 = (const float4*)(smem + c0 * HWN);
            const float4* s1 = (const float4*)(smem + c1 * HWN);
            float4* o0 = (float4*)(ot + c0 * HWN);
            float4* o1 = (float4*)(ot + c1 * HWN);
            #pragma unroll
            for (int k = 0; k < 7; k++) {
                const int j = lane + 32 * k;
                if (j < HW4) {
                    const float4 gt = s_gate4[j];
                    float4 a = s0[j];
                    float4 b = s1[j];
                    a.x *= gt.x; a.y *= gt.y; a.z *= gt.z; a.w *= gt.w;
                    b.x *= gt.x; b.y *= gt.y; b.z *= gt.z; b.w *= gt.w;
                    o0[j] = a;
                    o1[j] = b;
                }
            }
        }
        // smem (x tile + gate) is overwritten next iteration; barrier before reuse
        __syncthreads();
    }
}

extern "C" void kernel_launch(void* const* d_in, const int* in_sizes, int n_in,
                              void* d_out, int out_size)
{
    const float* x  = (const float*)d_in[0];
    const float* wt = (const float*)d_in[1];
    const float* bs = (const float*)d_in[2];
    float* out = (float*)d_out;

    cudaFuncSetAttribute(simam_wide_kernel,
                         cudaFuncAttributeMaxDynamicSharedMemorySize, SMEM_BYTES);
    simam_wide_kernel<<<GRID, NTHR, SMEM_BYTES>>>(x, wt, bs, out);
}